// round 1
// baseline (speedup 1.0000x reference)
#include <cuda_runtime.h>
#include <stdint.h>

// Problem constants (fixed by the dataset)
#define BB   16
#define NN   2048
#define CC   256
#define KK   16
#define KP1  17
#define OUTC 259   // 3 + C

// Scratch for knn indices (device global: allocation-free)
__device__ int g_knn[BB * NN * KK];

// ---------------------------------------------------------------------------
// Kernel A: pairwise d2 + top-17 selection (drop min == self), xyz deltas,
// and knn index emission.  One thread per query point; per-block SMEM holds
// the whole batch's (x,y,z,|x|^2) as float4 (broadcast LDS in the scan loop).
// ---------------------------------------------------------------------------
__global__ __launch_bounds__(128, 8)
void knn_kernel(const float* __restrict__ xyz, float* __restrict__ out)
{
    __shared__ float4 sp[NN];   // 32 KB: x, y, z, sq

    const int b   = blockIdx.y;
    const int tid = threadIdx.x;
    const float* xb = xyz + (size_t)b * NN * 3;

    // Stage batch points + squared norms
    for (int m = tid; m < NN; m += 128) {
        float x = xb[m * 3 + 0];
        float y = xb[m * 3 + 1];
        float z = xb[m * 3 + 2];
        float sq = x * x + y * y + z * z;
        sp[m] = make_float4(x, y, z, sq);
    }
    __syncthreads();

    const int n = blockIdx.x * 128 + tid;
    const float4 q = sp[n];

    // Register-resident top-17 smallest keys, key = (sortable(d2) << 32) | idx
    unsigned long long arr[KP1];
#pragma unroll
    for (int i = 0; i < KP1; i++) arr[i] = 0xFFFFFFFFFFFFFFFFULL;
    unsigned long long maxv = 0xFFFFFFFFFFFFFFFFULL;

    for (int m = 0; m < NN; m++) {
        float4 p = sp[m];                       // broadcast (all lanes same m)
        float dot = q.x * p.x + q.y * p.y + q.z * p.z;
        float d2  = q.w + p.w - 2.0f * dot;     // faithful to reference formula
        unsigned u = __float_as_uint(d2);
        u = (u & 0x80000000u) ? ~u : (u | 0x80000000u);   // order-preserving
        unsigned long long key = ((unsigned long long)u << 32) | (unsigned)m;
        if (key < maxv) {
            // replace first occurrence of current max (predicated, stays in regs)
            bool done = false;
#pragma unroll
            for (int i = 0; i < KP1; i++) {
                if (!done && arr[i] == maxv) { arr[i] = key; done = true; }
            }
            // recompute max
            maxv = arr[0];
#pragma unroll
            for (int i = 1; i < KP1; i++) maxv = (arr[i] > maxv) ? arr[i] : maxv;
        }
    }

    // The minimum key is "self" (sorted position 0 in the reference) -> drop it
    unsigned long long minv = arr[0];
#pragma unroll
    for (int i = 1; i < KP1; i++) minv = (arr[i] < minv) ? arr[i] : minv;

    float sx = 0.f, sy = 0.f, sz = 0.f;
    int jout = 0;
    int* knn_row = g_knn + ((size_t)b * NN + n) * KK;
#pragma unroll
    for (int i = 0; i < KP1; i++) {
        if (arr[i] != minv) {
            int idx = (int)(unsigned)(arr[i] & 0xFFFFFFFFULL);
            float4 p = sp[idx];
            sx += p.x; sy += p.y; sz += p.z;
            knn_row[jout++] = idx;
        }
    }

    const float inv = 1.0f / (float)KK;
    size_t ob = ((size_t)b * NN + n) * OUTC;
    out[ob + 0] = sx * inv - q.x;
    out[ob + 1] = sy * inv - q.y;
    out[ob + 2] = sz * inv - q.z;
}

// ---------------------------------------------------------------------------
// Kernel B: feature gather + mean - self.
// Block = (channel tile of 16, batch).  SMEM holds the 16x2048 feature slice
// (contiguous copy of the (B,C,N) layout).  Thread (c = tid>>4, j = tid&15)
// gathers one neighbor for one channel; shfl-reduce over the 16 j-lanes.
// ---------------------------------------------------------------------------
#define CT 16
__global__ __launch_bounds__(256, 1)
void gather_kernel(const float* __restrict__ features, float* __restrict__ out)
{
    extern __shared__ float fsm[];   // [CT][NN] = 128 KB

    const int b   = blockIdx.y;
    const int c0  = blockIdx.x * CT;
    const int tid = threadIdx.x;

    // Contiguous stage: rows c0..c0+15 of features[b] (layout matches gmem)
    const float* fb = features + ((size_t)b * CC + c0) * NN;
    for (int i = tid; i < CT * NN; i += 256) fsm[i] = fb[i];
    __syncthreads();

    const int c = tid >> 4;     // 0..15 (half-warp granularity)
    const int j = tid & 15;     // neighbor lane within half-warp

    const int*  knn_b = g_knn + (size_t)b * NN * KK;
    const float* frow = fsm + c * NN;
    float* outc = out + (size_t)b * NN * OUTC + 3 + c0 + c;

#pragma unroll 2
    for (int n = 0; n < NN; n++) {
        int nbr = knn_b[n * KK + j];      // 64B row, L1-resident broadcast
        float v = frow[nbr];              // random SMEM gather
        // reduce over 16 j-lanes (xor masks stay within the half-warp)
        v += __shfl_xor_sync(0xffffffffu, v, 8);
        v += __shfl_xor_sync(0xffffffffu, v, 4);
        v += __shfl_xor_sync(0xffffffffu, v, 2);
        v += __shfl_xor_sync(0xffffffffu, v, 1);
        if (j == 0) {
            outc[(size_t)n * OUTC] = v * (1.0f / (float)KK) - frow[n];
        }
    }
}

// ---------------------------------------------------------------------------
extern "C" void kernel_launch(void* const* d_in, const int* in_sizes, int n_in,
                              void* d_out, int out_size)
{
    const float* xyz      = (const float*)d_in[0];
    const float* features = (const float*)d_in[1];
    float* out = (float*)d_out;

    knn_kernel<<<dim3(NN / 128, BB), 128>>>(xyz, out);

    cudaFuncSetAttribute(gather_kernel,
                         cudaFuncAttributeMaxDynamicSharedMemorySize,
                         CT * NN * (int)sizeof(float));
    gather_kernel<<<dim3(CC / CT, BB), 256, CT * NN * sizeof(float)>>>(features, out);
}

// round 3
// speedup vs baseline: 5.7835x; 5.7835x over previous
#include <cuda_runtime.h>
#include <stdint.h>

// Problem constants (fixed by the dataset)
#define BB   16
#define NN   2048
#define CC   256
#define KK   16
#define KP1  17
#define OUTC 259   // 3 + C

// Scratch for knn indices (device global: allocation-free)
__device__ int g_knn[BB * NN * KK];

// ---------------------------------------------------------------------------
// Kernel A: pairwise d2 + exact top-17 (sorted register insertion list).
// One thread per query. dist[17] (u32 sortable fp32, FULL precision) + idx[17]
// kept sorted ascending; ties resolved by ascending index via strict compares.
// Sorted slot 0 == reference's dropped column 0 (self).
// ---------------------------------------------------------------------------
__global__ __launch_bounds__(256)
void knn_kernel(const float* __restrict__ xyz, float* __restrict__ out)
{
    __shared__ float4 sp[NN];   // 32 KB: x, y, z, |p|^2

    const int b   = blockIdx.y;
    const int tid = threadIdx.x;
    const float* xb = xyz + (size_t)b * NN * 3;

    for (int m = tid; m < NN; m += 256) {
        float x = xb[m * 3 + 0];
        float y = xb[m * 3 + 1];
        float z = xb[m * 3 + 2];
        sp[m] = make_float4(x, y, z, x * x + y * y + z * z);
    }
    __syncthreads();

    const int n = blockIdx.x * 256 + tid;
    const float4 q = sp[n];

    unsigned dist[KP1];
    int      idx [KP1];
#pragma unroll
    for (int i = 0; i < KP1; i++) { dist[i] = 0xFFFFFFFFu; idx[i] = 0; }

    for (int m = 0; m < NN; m++) {
        float4 p = sp[m];                       // broadcast LDS.128
        float dot = q.x * p.x + q.y * p.y + q.z * p.z;
        float d2  = q.w + p.w - 2.0f * dot;     // same formula as reference
        unsigned u = __float_as_uint(d2);
        u ^= ((unsigned)((int)u >> 31)) | 0x80000000u;   // order-preserving map

        if (u < dist[KP1 - 1]) {                // strict: tie vs 17th -> reject
            dist[KP1 - 1] = u;
            idx [KP1 - 1] = m;
            // branch-free bubble toward slot 0; stops below equal keys
#pragma unroll
            for (int i = KP1 - 1; i > 0; i--) {
                bool sw = dist[i] < dist[i - 1];        // strict -> stable ties
                unsigned dlo = min(dist[i], dist[i - 1]);
                unsigned dhi = max(dist[i], dist[i - 1]);
                int ilo = sw ? idx[i]     : idx[i - 1];
                int ihi = sw ? idx[i - 1] : idx[i];
                dist[i - 1] = dlo;  dist[i] = dhi;
                idx [i - 1] = ilo;  idx [i] = ihi;
            }
        }
    }

    // Slots 1..16 are the k neighbors (slot 0 == self / sorted column 0)
    float sx = 0.f, sy = 0.f, sz = 0.f;
    int* knn_row = g_knn + ((size_t)b * NN + n) * KK;
#pragma unroll
    for (int i = 1; i < KP1; i++) {
        int id = idx[i];
        float4 p = sp[id];
        sx += p.x; sy += p.y; sz += p.z;
        knn_row[i - 1] = id;
    }

    const float inv = 1.0f / (float)KK;
    size_t ob = ((size_t)b * NN + n) * OUTC;
    out[ob + 0] = sx * inv - q.x;
    out[ob + 1] = sy * inv - q.y;
    out[ob + 2] = sz * inv - q.z;
}

// ---------------------------------------------------------------------------
// Kernel B: feature gather + mean - self.
// Block = (16-channel tile, batch). SMEM rows padded to 2049 so the 16
// channel lanes reading the same neighbor index hit banks (c + idx) % 32 —
// conflict-free. Each thread owns one (c, n) output and runs the full k loop.
// ---------------------------------------------------------------------------
#define CT    16
#define PITCH 2049
#define SMEMB (CT * PITCH * (int)sizeof(float))

__global__ __launch_bounds__(256)
void gather_kernel(const float* __restrict__ features, float* __restrict__ out)
{
    extern __shared__ float fsm[];   // [CT][PITCH]

    const int b   = blockIdx.y;
    const int c0  = blockIdx.x * CT;
    const int tid = threadIdx.x;

    // Stage 16 channel rows (contiguous gmem) into padded SMEM rows
    const float* fb = features + ((size_t)b * CC + c0) * NN;
    for (int i = tid; i < CT * NN; i += 256) {
        int c = i >> 11;          // / NN
        int m = i & (NN - 1);
        fsm[c * PITCH + m] = fb[i];
    }
    __syncthreads();

    const int c  = tid & 15;
    const int n0 = tid >> 4;      // 0..15

    const int*   knn_b = g_knn + (size_t)b * NN * KK;
    const float* frow  = fsm + c * PITCH;
    float* outc = out + (size_t)b * NN * OUTC + 3 + c0 + c;

#pragma unroll 2
    for (int n = n0; n < NN; n += 16) {
        const int4* kr = (const int4*)(knn_b + n * KK);
        int4 k0 = __ldg(kr + 0);
        int4 k1 = __ldg(kr + 1);
        int4 k2 = __ldg(kr + 2);
        int4 k3 = __ldg(kr + 3);

        float s = frow[k0.x] + frow[k0.y] + frow[k0.z] + frow[k0.w]
                + frow[k1.x] + frow[k1.y] + frow[k1.z] + frow[k1.w]
                + frow[k2.x] + frow[k2.y] + frow[k2.z] + frow[k2.w]
                + frow[k3.x] + frow[k3.y] + frow[k3.z] + frow[k3.w];

        outc[(size_t)n * OUTC] = s * (1.0f / (float)KK) - frow[n];
    }
}

// ---------------------------------------------------------------------------
extern "C" void kernel_launch(void* const* d_in, const int* in_sizes, int n_in,
                              void* d_out, int out_size)
{
    const float* xyz      = (const float*)d_in[0];
    const float* features = (const float*)d_in[1];
    float* out = (float*)d_out;

    knn_kernel<<<dim3(NN / 256, BB), 256>>>(xyz, out);

    cudaFuncSetAttribute(gather_kernel,
                         cudaFuncAttributeMaxDynamicSharedMemorySize, SMEMB);
    gather_kernel<<<dim3(CC / CT, BB), 256, SMEMB>>>(features, out);
}

// round 5
// speedup vs baseline: 10.9300x; 1.8898x over previous
#include <cuda_runtime.h>
#include <stdint.h>

// Problem constants (fixed by the dataset)
#define BB   16
#define NN   2048
#define CC   256
#define KK   16
#define KP1  17
#define OUTC 259   // 3 + C

// Scratch for knn indices (device global: allocation-free)
__device__ int g_knn[BB * NN * KK];

// order-preserving fp32 -> u32 map
__device__ __forceinline__ unsigned f2u(float f) {
    unsigned u = __float_as_uint(f);
    return u ^ (((unsigned)((int)u >> 31)) | 0x80000000u);
}

// ---------------------------------------------------------------------------
// Kernel A: warp-per-query exact top-17.
// The 17 best (key=u32 sortable d2, payload=idx) live one-per-lane on lanes
// 0..16. Lanes scan 32 candidates per step; a ballot of "beats current 17th"
// is processed serially in ascending m (warp-UNIFORM control flow, no
// divergence). Eviction: among holders with key==max, evict largest idx
// (top_k tie semantics); strict accept keeps the incumbent on boundary ties.
// Keys+idx pairs are unique -> single-slot eviction always.
// ---------------------------------------------------------------------------
#define QW 8   // query warps per block (256 threads)
__global__ __launch_bounds__(256)
void knn_kernel(const float* __restrict__ xyz, float* __restrict__ out)
{
    __shared__ float4 sp[NN];   // 32 KB: x, y, z, |p|^2

    const int b    = blockIdx.y;
    const int tid  = threadIdx.x;
    const int lane = tid & 31;
    const int warp = tid >> 5;
    const float* xb = xyz + (size_t)b * NN * 3;

    for (int m = tid; m < NN; m += 256) {
        float x = xb[m * 3 + 0];
        float y = xb[m * 3 + 1];
        float z = xb[m * 3 + 2];
        sp[m] = make_float4(x, y, z, x * x + y * y + z * z);
    }
    __syncthreads();

    const int n = blockIdx.x * QW + warp;     // this warp's query
    const float4 q = sp[n];

    const bool holder = (lane < KP1);
    // distinct huge sentinels (real u keys for |d2|<1e30 are far below 0xFFFFFF00)
    unsigned ku   = holder ? (0xFFFFFF00u | (unsigned)lane) : 0u;
    unsigned kidx = 0u;
    unsigned maxu = 0xFFFFFF00u | (KP1 - 1);  // current 17th (max of holders)

    for (int step = 0; step < NN / 32; step++) {
        const int m = step * 32 + lane;
        float4 p = sp[m];                     // LDS.128, conflict-free
        float dot = q.x * p.x + q.y * p.y + q.z * p.z;
        float d2  = q.w + p.w - 2.0f * dot;   // same formula as reference
        unsigned u = f2u(d2);

        unsigned bal = __ballot_sync(0xffffffffu, u < maxu);
        while (bal) {                         // warp-uniform loop
            const int src = __ffs(bal) - 1;
            bal &= bal - 1;
            unsigned cu = __shfl_sync(0xffffffffu, u, src);
            unsigned cm = (unsigned)(step * 32 + src);
            if (cu < maxu) {                  // strict: boundary tie -> reject
                // evict: among holders with ku==maxu, the largest kidx
                bool ismax = holder && (ku == maxu);
                unsigned emx = __reduce_max_sync(0xffffffffu, ismax ? kidx : 0u);
                if (ismax && kidx == emx) { ku = cu; kidx = cm; }
                maxu = __reduce_max_sync(0xffffffffu, holder ? ku : 0u);
            }
        }
    }

    // identify self = min key, lowest idx among exact ties (sorted column 0)
    unsigned minu = __reduce_min_sync(0xffffffffu, holder ? ku : 0xFFFFFFFFu);
    bool ismin = holder && (ku == minu);
    unsigned mni = __reduce_min_sync(0xffffffffu, ismin ? kidx : 0xFFFFFFFFu);
    bool keep = holder && !(ismin && kidx == mni);

    // mean of neighbor xyz (16 keepers)
    float4 pN = make_float4(0.f, 0.f, 0.f, 0.f);
    if (keep) pN = sp[kidx];
    float sx = pN.x, sy = pN.y, sz = pN.z;
#pragma unroll
    for (int o = 16; o > 0; o >>= 1) {
        sx += __shfl_xor_sync(0xffffffffu, sx, o);
        sy += __shfl_xor_sync(0xffffffffu, sy, o);
        sz += __shfl_xor_sync(0xffffffffu, sz, o);
    }
    if (lane == 0) {
        const float inv = 1.0f / (float)KK;
        size_t ob = ((size_t)b * NN + n) * OUTC;
        out[ob + 0] = sx * inv - q.x;
        out[ob + 1] = sy * inv - q.y;
        out[ob + 2] = sz * inv - q.z;
    }

    // emit knn indices (order within row irrelevant: gather sums them)
    unsigned kb = __ballot_sync(0xffffffffu, keep);
    int pos = __popc(kb & ((1u << lane) - 1u));
    if (keep) g_knn[((size_t)b * NN + n) * KK + pos] = (int)kidx;
}

// ---------------------------------------------------------------------------
// Kernel B: feature gather + mean - self.
// Block = (16-channel tile, batch), 512 threads (16 warps for latency hiding).
// SMEM rows padded to 2049: the 16 channel lanes of a group read banks
// (c + idx) % 32 — conflict-free within the group.
// ---------------------------------------------------------------------------
#define CT    16
#define PITCH 2049
#define SMEMB (CT * PITCH * (int)sizeof(float))

__global__ __launch_bounds__(512)
void gather_kernel(const float* __restrict__ features, float* __restrict__ out)
{
    extern __shared__ float fsm[];   // [CT][PITCH]

    const int b   = blockIdx.y;
    const int c0  = blockIdx.x * CT;
    const int tid = threadIdx.x;

    // Stage 16 channel rows (contiguous gmem) into padded SMEM rows
    const float* fb = features + ((size_t)b * CC + c0) * NN;
    for (int i = tid; i < CT * NN; i += 512) {
        int c = i >> 11;          // / NN
        int m = i & (NN - 1);
        fsm[c * PITCH + m] = fb[i];
    }
    __syncthreads();

    const int c  = tid & 15;
    const int n0 = tid >> 4;      // 0..31

    const int*   knn_b = g_knn + (size_t)b * NN * KK;
    const float* frow  = fsm + c * PITCH;
    float* outc = out + (size_t)b * NN * OUTC + 3 + c0 + c;

#pragma unroll 2
    for (int n = n0; n < NN; n += 32) {
        const int4* kr = (const int4*)(knn_b + n * KK);
        int4 k0 = __ldg(kr + 0);
        int4 k1 = __ldg(kr + 1);
        int4 k2 = __ldg(kr + 2);
        int4 k3 = __ldg(kr + 3);

        float s = frow[k0.x] + frow[k0.y] + frow[k0.z] + frow[k0.w]
                + frow[k1.x] + frow[k1.y] + frow[k1.z] + frow[k1.w]
                + frow[k2.x] + frow[k2.y] + frow[k2.z] + frow[k2.w]
                + frow[k3.x] + frow[k3.y] + frow[k3.z] + frow[k3.w];

        outc[(size_t)n * OUTC] = s * (1.0f / (float)KK) - frow[n];
    }
}

// ---------------------------------------------------------------------------
extern "C" void kernel_launch(void* const* d_in, const int* in_sizes, int n_in,
                              void* d_out, int out_size)
{
    const float* xyz      = (const float*)d_in[0];
    const float* features = (const float*)d_in[1];
    float* out = (float*)d_out;

    knn_kernel<<<dim3(NN / QW, BB), 256>>>(xyz, out);

    cudaFuncSetAttribute(gather_kernel,
                         cudaFuncAttributeMaxDynamicSharedMemorySize, SMEMB);
    gather_kernel<<<dim3(CC / CT, BB), 512, SMEMB>>>(features, out);
}